// round 1
// baseline (speedup 1.0000x reference)
#include <cuda_runtime.h>
#include <cstdint>
#include <cstddef>

#define N_TOK   8192
#define IN_DIMC 1024
#define HIDC    2048
#define NE      4
#define TEDC    100
#define MU_C    0.01f
#define EPS_C   1e-6f

// Scratch (allocation-free rule: __device__ globals)
__device__ float g_H[(size_t)NE * N_TOK * HIDC];   // relu(X@W1+b1), expert-major
__device__ float g_O[(size_t)NE * N_TOK * HIDC];   // relu(H@W2+b2), expert-major
__device__ float g_gate[N_TOK];
__device__ int   g_idx[N_TOK];

typedef unsigned long long ull;

__device__ __forceinline__ ull pack2(float x, float y) {
    ull r; asm("mov.b64 %0, {%1, %2};" : "=l"(r) : "f"(x), "f"(y)); return r;
}
__device__ __forceinline__ float2 unpack2(ull v) {
    float2 r; asm("mov.b64 {%0, %1}, %2;" : "=f"(r.x), "=f"(r.y) : "l"(v)); return r;
}
// Packed dual-FMA: 2x fp32 FMA throughput vs 3-reg FFMA on sm_103a (PTX-only form)
__device__ __forceinline__ ull ffma2(ull a, ull b, ull c) {
    ull d; asm("fma.rn.f32x2 %0, %1, %2, %3;" : "=l"(d) : "l"(a), "l"(b), "l"(c)); return d;
}

// ---------------------------------------------------------------------------
// Router: logits = [X | temb[task]] @ rmat[1124,4]; softmax; argmax; gate; reg
// One warp per token. rmat rows are exactly float4 (E=4).
// ---------------------------------------------------------------------------
__global__ void router_kernel(const float* __restrict__ X,
                              const int*   __restrict__ task,
                              const float* __restrict__ temb,
                              const float* __restrict__ rmat,
                              float* __restrict__ gate,
                              int*   __restrict__ idxOut,
                              float* __restrict__ regLoss)
{
    int warp = (blockIdx.x * blockDim.x + threadIdx.x) >> 5;
    int lane = threadIdx.x & 31;
    if (warp >= N_TOK) return;

    const float* x  = X + (size_t)warp * IN_DIMC;
    const float* te = temb + (size_t)task[warp] * TEDC;
    const float4* r4 = (const float4*)rmat;

    float a0 = 0.f, a1 = 0.f, a2 = 0.f, a3 = 0.f;
    for (int k = lane; k < IN_DIMC; k += 32) {
        float xv = x[k]; float4 r = r4[k];
        a0 += xv * r.x; a1 += xv * r.y; a2 += xv * r.z; a3 += xv * r.w;
    }
    for (int k = lane; k < TEDC; k += 32) {
        float xv = te[k]; float4 r = r4[IN_DIMC + k];
        a0 += xv * r.x; a1 += xv * r.y; a2 += xv * r.z; a3 += xv * r.w;
    }
    #pragma unroll
    for (int o = 16; o; o >>= 1) {
        a0 += __shfl_xor_sync(0xffffffffu, a0, o);
        a1 += __shfl_xor_sync(0xffffffffu, a1, o);
        a2 += __shfl_xor_sync(0xffffffffu, a2, o);
        a3 += __shfl_xor_sync(0xffffffffu, a3, o);
    }
    if (lane == 0) {
        float l[4] = {a0, a1, a2, a3};
        int best = 0; float bm = l[0];
        #pragma unroll
        for (int e = 1; e < 4; e++) if (l[e] > bm) { bm = l[e]; best = e; }  // first-occurrence argmax
        float s = 0.f;
        #pragma unroll
        for (int e = 0; e < 4; e++) s += expf(l[e] - bm);
        float g = 1.0f / s;  // softmax weight of the winner
        gate[warp]   = g;
        idxOut[warp] = best;
        // gates one-hot: sum log(gates+eps) = log(g+eps) + (E-1)*log(eps)
        regLoss[warp] = -(MU_C / (float)NE) * (logf(g + EPS_C) + 3.0f * logf(EPS_C));
    }
}

// ---------------------------------------------------------------------------
// Batched GEMM + bias + relu.  C[e] = relu(A[e] @ B[e] + bias[e])
// A: [M,K] row-major (M=8192), B: [K,2048] row-major, C: [M,2048].
// 128x128 tile, BK=16, double-buffered smem, 8x8 per thread, f32x2 FMAs.
// All dims divide tiles exactly (8192/128, 2048/128, K%16==0) — no guards.
// ---------------------------------------------------------------------------
__global__ __launch_bounds__(256, 2)
void gemm_bias_relu(const float* __restrict__ A, const float* __restrict__ B,
                    const float* __restrict__ bias, float* __restrict__ C,
                    int K, size_t aES, size_t bES, size_t biasES, size_t cES)
{
    __shared__ float As[2][16][128];   // transposed: As[k][m]
    __shared__ float Bs[2][16][128];   // Bs[k][n]

    int e = blockIdx.z;
    const float* Ae    = A    + (size_t)e * aES;
    const float* Be    = B    + (size_t)e * bES;
    const float* biasE = bias + (size_t)e * biasES;
    float*       Ce    = C    + (size_t)e * cES;

    int tid = threadIdx.x;
    int tx  = tid & 15;          // 16 col-groups of 8
    int ty  = tid >> 4;          // 16 row-groups of 8
    int m0  = blockIdx.y * 128;
    int n0  = blockIdx.x * 128;

    // A tile loader: thread -> row tid>>1, k-half (tid&1)*8, two float4 along k
    int aRow = tid >> 1;
    int aKb  = (tid & 1) * 8;
    const float* aPtr = Ae + (size_t)(m0 + aRow) * K + aKb;
    // B tile loader: thread -> k-row tid>>4, 8 consecutive n, two float4 along n
    int bRow = tid >> 4;
    int bCol = (tid & 15) * 8;
    const float* bPtr = Be + (size_t)bRow * HIDC + n0 + bCol;

    ull acc[8][4];
    #pragma unroll
    for (int i = 0; i < 8; i++)
        #pragma unroll
        for (int j = 0; j < 4; j++) acc[i][j] = 0ULL;

    // prologue: stage tile 0
    {
        float4 xa0 = *(const float4*)(aPtr);
        float4 xa1 = *(const float4*)(aPtr + 4);
        As[0][aKb+0][aRow] = xa0.x; As[0][aKb+1][aRow] = xa0.y;
        As[0][aKb+2][aRow] = xa0.z; As[0][aKb+3][aRow] = xa0.w;
        As[0][aKb+4][aRow] = xa1.x; As[0][aKb+5][aRow] = xa1.y;
        As[0][aKb+6][aRow] = xa1.z; As[0][aKb+7][aRow] = xa1.w;
        float4 xb0 = *(const float4*)(bPtr);
        float4 xb1 = *(const float4*)(bPtr + 4);
        *(float4*)&Bs[0][bRow][bCol]     = xb0;
        *(float4*)&Bs[0][bRow][bCol + 4] = xb1;
    }
    __syncthreads();

    int nT = K >> 4;
    float4 pa0, pa1, pb0, pb1;
    for (int tt = 0; tt < nT; tt++) {
        int buf = tt & 1;
        if (tt + 1 < nT) {
            const float* ap = aPtr + (tt + 1) * 16;
            pa0 = *(const float4*)(ap);
            pa1 = *(const float4*)(ap + 4);
            const float* bp = bPtr + (size_t)(tt + 1) * 16 * HIDC;
            pb0 = *(const float4*)(bp);
            pb1 = *(const float4*)(bp + 4);
        }
        #pragma unroll
        for (int k = 0; k < 16; k++) {
            float4 a0 = *(const float4*)&As[buf][k][ty * 8];
            float4 a1 = *(const float4*)&As[buf][k][ty * 8 + 4];
            float4 b0 = *(const float4*)&Bs[buf][k][tx * 8];
            float4 b1 = *(const float4*)&Bs[buf][k][tx * 8 + 4];
            ull bp2[4] = { pack2(b0.x, b0.y), pack2(b0.z, b0.w),
                           pack2(b1.x, b1.y), pack2(b1.z, b1.w) };
            float av[8] = {a0.x, a0.y, a0.z, a0.w, a1.x, a1.y, a1.z, a1.w};
            #pragma unroll
            for (int i = 0; i < 8; i++) {
                ull ap2 = pack2(av[i], av[i]);
                #pragma unroll
                for (int j = 0; j < 4; j++) acc[i][j] = ffma2(ap2, bp2[j], acc[i][j]);
            }
        }
        if (tt + 1 < nT) {
            As[buf^1][aKb+0][aRow] = pa0.x; As[buf^1][aKb+1][aRow] = pa0.y;
            As[buf^1][aKb+2][aRow] = pa0.z; As[buf^1][aKb+3][aRow] = pa0.w;
            As[buf^1][aKb+4][aRow] = pa1.x; As[buf^1][aKb+5][aRow] = pa1.y;
            As[buf^1][aKb+6][aRow] = pa1.z; As[buf^1][aKb+7][aRow] = pa1.w;
            *(float4*)&Bs[buf^1][bRow][bCol]     = pb0;
            *(float4*)&Bs[buf^1][bRow][bCol + 4] = pb1;
        }
        __syncthreads();
    }

    // epilogue: bias + relu + store
    float4 bv0 = *(const float4*)(biasE + n0 + tx * 8);
    float4 bv1 = *(const float4*)(biasE + n0 + tx * 8 + 4);
    #pragma unroll
    for (int i = 0; i < 8; i++) {
        float* crow = Ce + (size_t)(m0 + ty * 8 + i) * HIDC + n0 + tx * 8;
        float2 v0 = unpack2(acc[i][0]);
        float2 v1 = unpack2(acc[i][1]);
        float2 v2 = unpack2(acc[i][2]);
        float2 v3 = unpack2(acc[i][3]);
        float4 o0, o1;
        o0.x = fmaxf(v0.x + bv0.x, 0.f);
        o0.y = fmaxf(v0.y + bv0.y, 0.f);
        o0.z = fmaxf(v1.x + bv0.z, 0.f);
        o0.w = fmaxf(v1.y + bv0.w, 0.f);
        o1.x = fmaxf(v2.x + bv1.x, 0.f);
        o1.y = fmaxf(v2.y + bv1.y, 0.f);
        o1.z = fmaxf(v3.x + bv1.z, 0.f);
        o1.w = fmaxf(v3.y + bv1.w, 0.f);
        *(float4*)(crow)     = o0;
        *(float4*)(crow + 4) = o1;
    }
}

// ---------------------------------------------------------------------------
// Gram-Schmidt + top-1 gather. One block per token, 256 threads x 8 elems.
// Only computes basis vectors 0..idx[n] (all later ones are unused).
// ---------------------------------------------------------------------------
template <int M>
__device__ __forceinline__ void blockReduce(float* vals, float (*red)[8], int tid)
{
    int lane = tid & 31, w = tid >> 5;
    #pragma unroll
    for (int i = 0; i < M; i++) {
        float v = vals[i];
        #pragma unroll
        for (int o = 16; o; o >>= 1) v += __shfl_xor_sync(0xffffffffu, v, o);
        if (lane == 0) red[i][w] = v;
    }
    __syncthreads();
    #pragma unroll
    for (int i = 0; i < M; i++) {
        float s = 0.f;
        #pragma unroll
        for (int ww = 0; ww < 8; ww++) s += red[i][ww];  // same order everywhere -> identical value
        vals[i] = s;
    }
    __syncthreads();
}

__global__ void gs_kernel(const float* __restrict__ O,
                          const float* __restrict__ gate,
                          const int*   __restrict__ idx,
                          float* __restrict__ out)
{
    __shared__ float red[3][8];
    int n   = blockIdx.x;
    int tid = threadIdx.x;
    int kmax = idx[n];          // uniform across the block
    float g  = gate[n];
    const size_t NH = (size_t)N_TOK * HIDC;
    const float* base = O + (size_t)n * HIDC + tid * 8;

    float b[4][8];
    float t[8], w[8];

    #pragma unroll
    for (int i = 0; i < 4; i++) {
        if (i > kmax) break;
        float4 p0 = *(const float4*)(base + (size_t)i * NH);
        float4 p1 = *(const float4*)(base + (size_t)i * NH + 4);
        t[0]=p0.x; t[1]=p0.y; t[2]=p0.z; t[3]=p0.w;
        t[4]=p1.x; t[5]=p1.y; t[6]=p1.z; t[7]=p1.w;

        float c[3] = {0.f, 0.f, 0.f};
        if (i > 0) {
            #pragma unroll
            for (int j = 0; j < 3; j++) {
                if (j < i) {
                    float d = 0.f;
                    #pragma unroll
                    for (int q = 0; q < 8; q++) d += t[q] * b[j][q];
                    c[j] = d;
                }
            }
            blockReduce<3>(c, red, tid);
        }
        float ss[1] = {0.f};
        #pragma unroll
        for (int q = 0; q < 8; q++) {
            float wv = t[q];
            #pragma unroll
            for (int j = 0; j < 3; j++) if (j < i) wv -= c[j] * b[j][q];
            w[q] = wv;
            ss[0] += wv * wv;
        }
        blockReduce<1>(ss, red, tid);
        float inv = rsqrtf(ss[0]);
        #pragma unroll
        for (int q = 0; q < 8; q++) b[i][q] = w[q] * inv;

        if (i == kmax) {
            float4 o0, o1;
            o0.x = g * b[i][0]; o0.y = g * b[i][1];
            o0.z = g * b[i][2]; o0.w = g * b[i][3];
            o1.x = g * b[i][4]; o1.y = g * b[i][5];
            o1.z = g * b[i][6]; o1.w = g * b[i][7];
            float* op = out + (size_t)n * HIDC + tid * 8;
            *(float4*)(op)     = o0;
            *(float4*)(op + 4) = o1;
        }
    }
}

// ---------------------------------------------------------------------------
extern "C" void kernel_launch(void* const* d_in, const int* in_sizes, int n_in,
                              void* d_out, int out_size)
{
    const float* X    = (const float*)d_in[0];
    const int*   task = (const int*)  d_in[1];
    const float* temb = (const float*)d_in[2];
    const float* rmat = (const float*)d_in[3];
    const float* W1   = (const float*)d_in[4];
    const float* b1   = (const float*)d_in[5];
    const float* W2   = (const float*)d_in[6];
    const float* b2   = (const float*)d_in[7];
    float* out = (float*)d_out;

    float *H, *O, *gate; int* idx;
    cudaGetSymbolAddress((void**)&H,    g_H);
    cudaGetSymbolAddress((void**)&O,    g_O);
    cudaGetSymbolAddress((void**)&gate, g_gate);
    cudaGetSymbolAddress((void**)&idx,  g_idx);

    // reg_loss lives after the [N, HID] tower_input in the flattened output
    router_kernel<<<N_TOK / 8, 256>>>(X, task, temb, rmat, gate, idx,
                                      out + (size_t)N_TOK * HIDC);

    dim3 g1(HIDC / 128, N_TOK / 128, NE);
    gemm_bias_relu<<<g1, 256>>>(X, W1, b1, H, IN_DIMC,
                                (size_t)0, (size_t)IN_DIMC * HIDC,
                                (size_t)HIDC, (size_t)N_TOK * HIDC);
    gemm_bias_relu<<<g1, 256>>>(H, W2, b2, O, HIDC,
                                (size_t)N_TOK * HIDC, (size_t)HIDC * HIDC,
                                (size_t)HIDC, (size_t)N_TOK * HIDC);

    gs_kernel<<<N_TOK, 256>>>(O, gate, idx, out);
}

// round 10
// speedup vs baseline: 3.5373x; 3.5373x over previous
#include <cuda_runtime.h>
#include <cuda_bf16.h>
#include <cstdint>
#include <cstddef>

#define N_TOK   8192
#define IN_DIMC 1024
#define HIDC    2048
#define NE      4
#define TEDC    100
#define MU_C    0.01f
#define EPS_C   1e-6f

typedef __nv_bfloat16 bf16;

// ---------------- scratch (__device__ globals; no allocations) --------------
__device__ bf16  g_Xhi [(size_t)N_TOK * IN_DIMC];        // compacted rows
__device__ bf16  g_Xlo [(size_t)N_TOK * IN_DIMC];
__device__ bf16  g_W1Thi[(size_t)NE * HIDC * IN_DIMC];   // [e][n][k]
__device__ bf16  g_W1Tlo[(size_t)NE * HIDC * IN_DIMC];
__device__ bf16  g_W2Thi[(size_t)NE * HIDC * HIDC];      // [e][n][k]
__device__ bf16  g_W2Tlo[(size_t)NE * HIDC * HIDC];
__device__ bf16  g_Hhi [(size_t)NE * N_TOK * HIDC];      // compacted rows
__device__ bf16  g_Hlo [(size_t)NE * N_TOK * HIDC];
__device__ float g_O   [(size_t)NE * N_TOK * HIDC];      // compacted rows
__device__ float g_gate[N_TOK];
__device__ int   g_idx [N_TOK];
__device__ int   g_pos [N_TOK];          // token -> compacted position
__device__ int   g_perm[N_TOK];          // compacted position -> token
__device__ int   g_cnt[NE];              // histogram of idx
__device__ int   g_off[NE];              // atomic cursors
__device__ int   g_start[NE];            // bucket starts (desc order)
__device__ int   g_cntge[NE];            // #tokens with idx >= e

// ---------------- PTX helpers ------------------------------------------------
__device__ __forceinline__ uint32_t smem_u32(const void* p) {
    uint32_t a;
    asm("{ .reg .u64 t; cvta.to.shared.u64 t, %1; cvt.u32.u64 %0, t; }"
        : "=r"(a) : "l"(p));
    return a;
}
#define CPASYNC16(s, g) \
    asm volatile("cp.async.cg.shared.global [%0], [%1], 16;" \
                 :: "r"(s), "l"(g) : "memory")
#define CP_COMMIT() asm volatile("cp.async.commit_group;" ::: "memory")
#define CP_WAIT(n)  asm volatile("cp.async.wait_group %0;" :: "n"(n) : "memory")
#define LDMX4(R, addr) \
    asm volatile("ldmatrix.sync.aligned.m8n8.x4.shared.b16 {%0,%1,%2,%3}, [%4];" \
                 : "=r"((R)[0]), "=r"((R)[1]), "=r"((R)[2]), "=r"((R)[3]) \
                 : "r"(addr))
#define MMA16816(C, A, B) \
    asm volatile("mma.sync.aligned.m16n8k16.row.col.f32.bf16.bf16.f32 " \
                 "{%0,%1,%2,%3},{%4,%5,%6,%7},{%8,%9},{%0,%1,%2,%3};" \
                 : "+f"((C)[0]), "+f"((C)[1]), "+f"((C)[2]), "+f"((C)[3]) \
                 : "r"((A)[0]), "r"((A)[1]), "r"((A)[2]), "r"((A)[3]), \
                   "r"((B)[0]), "r"((B)[1]))

// [128 rows][4 data chunks of 16B] staged with row stride of FIVE chunks.
// chunk = r*5 + c; 5 is invertible mod 8 => 8 consecutive rows at fixed c
// hit 8 distinct 16B bank groups: conflict-free ldmatrix and STS.
__device__ __forceinline__ uint32_t swz(int r, int c) {
    return (uint32_t)((r * 5 + c) * 16);
}

// ---------------- router -----------------------------------------------------
__global__ void router_kernel(const float* __restrict__ X,
                              const int*   __restrict__ task,
                              const float* __restrict__ temb,
                              const float* __restrict__ rmat,
                              float* __restrict__ gate,
                              int*   __restrict__ idxOut,
                              float* __restrict__ regLoss)
{
    int warp = (blockIdx.x * blockDim.x + threadIdx.x) >> 5;
    int lane = threadIdx.x & 31;
    if (warp >= N_TOK) return;

    const float* x  = X + (size_t)warp * IN_DIMC;
    const float* te = temb + (size_t)task[warp] * TEDC;
    const float4* r4 = (const float4*)rmat;

    float a0 = 0.f, a1 = 0.f, a2 = 0.f, a3 = 0.f;
    for (int k = lane; k < IN_DIMC; k += 32) {
        float xv = x[k]; float4 r = r4[k];
        a0 += xv * r.x; a1 += xv * r.y; a2 += xv * r.z; a3 += xv * r.w;
    }
    for (int k = lane; k < TEDC; k += 32) {
        float xv = te[k]; float4 r = r4[IN_DIMC + k];
        a0 += xv * r.x; a1 += xv * r.y; a2 += xv * r.z; a3 += xv * r.w;
    }
    #pragma unroll
    for (int o = 16; o; o >>= 1) {
        a0 += __shfl_xor_sync(0xffffffffu, a0, o);
        a1 += __shfl_xor_sync(0xffffffffu, a1, o);
        a2 += __shfl_xor_sync(0xffffffffu, a2, o);
        a3 += __shfl_xor_sync(0xffffffffu, a3, o);
    }
    if (lane == 0) {
        float l[4] = {a0, a1, a2, a3};
        int best = 0; float bm = l[0];
        #pragma unroll
        for (int e = 1; e < 4; e++) if (l[e] > bm) { bm = l[e]; best = e; }
        float s = 0.f;
        #pragma unroll
        for (int e = 0; e < 4; e++) s += expf(l[e] - bm);
        float g = 1.0f / s;
        gate[warp]   = g;
        idxOut[warp] = best;
        regLoss[warp] = -(MU_C / (float)NE) * (logf(g + EPS_C) + 3.0f * logf(EPS_C));
    }
}

// ---------------- compaction -------------------------------------------------
__global__ void init_cnt_kernel(int* cnt, int* off) {
    if (threadIdx.x < NE) { cnt[threadIdx.x] = 0; off[threadIdx.x] = 0; }
}
__global__ void hist_kernel(const int* __restrict__ idx, int* cnt) {
    int n = blockIdx.x * blockDim.x + threadIdx.x;
    if (n < N_TOK) atomicAdd(&cnt[idx[n]], 1);
}
__global__ void scan_kernel(const int* __restrict__ cnt,
                            int* start, int* cntge) {
    if (threadIdx.x == 0) {
        // descending-idx bucket order: 3,2,1,0
        int s = 0;
        for (int e = NE - 1; e >= 0; e--) { start[e] = s; s += cnt[e]; }
        for (int e = 0; e < NE; e++) cntge[e] = start[e] + cnt[e];
    }
}
__global__ void pos_kernel(const int* __restrict__ idx,
                           const int* __restrict__ start,
                           int* off, int* pos, int* perm) {
    int n = blockIdx.x * blockDim.x + threadIdx.x;
    if (n >= N_TOK) return;
    int e = idx[n];
    int p = start[e] + atomicAdd(&off[e], 1);
    pos[n] = p;
    perm[p] = n;
}

// ---------------- gather + fp32 -> bf16 hi/lo split -------------------------
__global__ void gather_split_kernel(const float* __restrict__ X,
                                    const int* __restrict__ perm,
                                    bf16* __restrict__ hi, bf16* __restrict__ lo)
{
    size_t i = (size_t)blockIdx.x * blockDim.x + threadIdx.x;   // float4 units
    if (i >= (size_t)N_TOK * IN_DIMC / 4) return;
    int row = (int)(i >> 8);                 // IN_DIMC/4 = 256
    int c4  = (int)(i & 255);
    int src = perm[row];
    float4 v = *(const float4*)(X + (size_t)src * IN_DIMC + c4 * 4);
    float f[4] = {v.x, v.y, v.z, v.w};
    union { unsigned short u[4]; uint2 q; } H, L;
    #pragma unroll
    for (int j = 0; j < 4; j++) {
        bf16 h = __float2bfloat16(f[j]);
        bf16 l = __float2bfloat16(f[j] - __bfloat162float(h));
        H.u[j] = __bfloat16_as_ushort(h);
        L.u[j] = __bfloat16_as_ushort(l);
    }
    ((uint2*)hi)[i] = H.q;
    ((uint2*)lo)[i] = L.q;
}

// ---------------- W [e][K][N] f32 -> [e][N][K] bf16 hi/lo -------------------
__global__ void transpose_split(const float* __restrict__ W,
                                bf16* __restrict__ Thi, bf16* __restrict__ Tlo,
                                int K, int N)
{
    __shared__ float tile[32][33];
    int e  = blockIdx.z;
    int k0 = blockIdx.y * 32, n0 = blockIdx.x * 32;
    const float* We = W + (size_t)e * K * N;
    for (int r = threadIdx.y; r < 32; r += 8)
        tile[r][threadIdx.x] = We[(size_t)(k0 + r) * N + n0 + threadIdx.x];
    __syncthreads();
    size_t ebase = (size_t)e * K * N;
    for (int r = threadIdx.y; r < 32; r += 8) {
        float v = tile[threadIdx.x][r];
        bf16 h = __float2bfloat16(v);
        bf16 l = __float2bfloat16(v - __bfloat162float(h));
        size_t o = ebase + (size_t)(n0 + r) * K + k0 + threadIdx.x;
        Thi[o] = h; Tlo[o] = l;
    }
}

// ---------------------------------------------------------------------------
// HMMA bf16 3-pass GEMM: D[m][n] = sum_k A[m][k]*B[n][k], A=Ahi+Alo, B=Bhi+Blo
// (hh + hl + lh passes, shared fp32 accumulators). CTA tile 128x128, BK=32.
// 8 warps as 2(m) x 4(n); warp tile 64x32. cp.async 3-stage pipeline.
// mode 0: out = relu(D+bias) -> bf16 hi/lo; mode 1: -> f32.
// CTAs with m0 >= cntge[e] exit immediately (expert skipping).
// ---------------------------------------------------------------------------
#define TILEB  10240         // [128 rows][5 chunks x 16B] (4 data + 1 pad)
#define STAGEB (4 * TILEB)   // Ahi Alo Bhi Blo
#define NSTAGE 3
#define GEMM_SMEM (NSTAGE * STAGEB)   // 122880

__global__ __launch_bounds__(256, 1)
void gemm_hmma(const bf16* __restrict__ Ahi, const bf16* __restrict__ Alo,
               const bf16* __restrict__ Bhi, const bf16* __restrict__ Blo,
               const float* __restrict__ bias,
               bf16* __restrict__ OutHi, bf16* __restrict__ OutLo,
               float* __restrict__ OutF,
               const int* __restrict__ cntge,
               int K, int mode,
               size_t aES, size_t bES, size_t biasES, size_t oES)
{
    int e  = blockIdx.z;
    int m0 = blockIdx.y * 128;
    if (m0 >= cntge[e]) return;        // expert skipping
    int n0 = blockIdx.x * 128;

    extern __shared__ __align__(128) char smem[];
    uint32_t sbase = smem_u32(smem);

    int tid  = threadIdx.x;
    int wid  = tid >> 5, lane = tid & 31;
    int wm0  = (wid & 1) * 64;
    int wn0  = (wid >> 1) * 32;

    const bf16* gAh = Ahi + e * aES + (size_t)m0 * K;
    const bf16* gAl = Alo + e * aES + (size_t)m0 * K;
    const bf16* gBh = Bhi + e * bES + (size_t)n0 * K;
    const bf16* gBl = Blo + e * bES + (size_t)n0 * K;

    int nT = K >> 5;

    // accumulators: 4 m-tiles x 4 n-tiles x 4 regs
    float acc[4][4][4];
    #pragma unroll
    for (int i = 0; i < 4; i++)
        #pragma unroll
        for (int j = 0; j < 4; j++)
            #pragma unroll
            for (int q = 0; q < 4; q++) acc[i][j][q] = 0.f;

    // loader: thread covers data chunks 2*tid, 2*tid+1 of each 512-chunk tile
    int j0 = tid * 2;

    #define ISSUE(t)                                                         \
        do {                                                                 \
            if ((t) < nT) {                                                  \
                uint32_t sb_ = sbase + ((t) % NSTAGE) * STAGEB;              \
                _Pragma("unroll")                                            \
                for (int q_ = 0; q_ < 2; q_++) {                             \
                    int j_ = j0 + q_;                                        \
                    int r_ = j_ >> 2, c_ = j_ & 3;                           \
                    uint32_t so_ = swz(r_, c_);                              \
                    size_t go_ = (size_t)r_ * K + (size_t)(t) * 32 + c_ * 8; \
                    CPASYNC16(sb_ + 0 * TILEB + so_, gAh + go_);             \
                    CPASYNC16(sb_ + 1 * TILEB + so_, gAl + go_);             \
                    CPASYNC16(sb_ + 2 * TILEB + so_, gBh + go_);             \
                    CPASYNC16(sb_ + 3 * TILEB + so_, gBl + go_);             \
                }                                                            \
            }                                                                \
            CP_COMMIT();                                                     \
        } while (0)

    ISSUE(0);
    ISSUE(1);

    for (int t = 0; t < nT; t++) {
        CP_WAIT(1);            // stage t complete (only t+1 may be pending)
        __syncthreads();       // also orders prior compute before next ISSUE

        uint32_t sb  = sbase + (t % NSTAGE) * STAGEB;
        uint32_t sAh = sb, sAl = sb + TILEB, sBh = sb + 2 * TILEB, sBl = sb + 3 * TILEB;

        #pragma unroll
        for (int ks = 0; ks < 2; ks++) {
            int kc = ks * 2;
            uint32_t Ah[4][4], Al[4][4], Bh[2][4], Bl[2][4];
            #pragma unroll
            for (int mi = 0; mi < 4; mi++) {
                int row = wm0 + mi * 16 + (lane & 15);
                int c   = kc + (lane >> 4);
                uint32_t off = swz(row, c);
                LDMX4(Ah[mi], sAh + off);
                LDMX4(Al[mi], sAl + off);
            }
            #pragma unroll
            for (int bi = 0; bi < 2; bi++) {
                int row = wn0 + bi * 16 + ((lane >> 4) & 1) * 8 + (lane & 7);
                int c   = kc + ((lane >> 3) & 1);
                uint32_t off = swz(row, c);
                LDMX4(Bh[bi], sBh + off);
                LDMX4(Bl[bi], sBl + off);
            }
            #pragma unroll
            for (int mi = 0; mi < 4; mi++) {
                #pragma unroll
                for (int ni = 0; ni < 4; ni++) {
                    uint32_t* bh = &Bh[ni >> 1][(ni & 1) * 2];
                    uint32_t* bl = &Bl[ni >> 1][(ni & 1) * 2];
                    MMA16816(acc[mi][ni], Ah[mi], bh);   // hi*hi
                    MMA16816(acc[mi][ni], Ah[mi], bl);   // hi*lo
                    MMA16816(acc[mi][ni], Al[mi], bh);   // lo*hi
                }
            }
        }
        ISSUE(t + 2);
    }

    // epilogue
    const float* biasE = bias + e * biasES;
    #pragma unroll
    for (int mi = 0; mi < 4; mi++) {
        #pragma unroll
        for (int ni = 0; ni < 4; ni++) {
            int gr0 = m0 + wm0 + mi * 16 + (lane >> 2);
            int gr1 = gr0 + 8;
            int gc  = n0 + wn0 + ni * 8 + (lane & 3) * 2;
            float bv0 = __ldg(biasE + gc), bv1 = __ldg(biasE + gc + 1);
            float f00 = fmaxf(acc[mi][ni][0] + bv0, 0.f);
            float f01 = fmaxf(acc[mi][ni][1] + bv1, 0.f);
            float f10 = fmaxf(acc[mi][ni][2] + bv0, 0.f);
            float f11 = fmaxf(acc[mi][ni][3] + bv1, 0.f);
            if (mode == 0) {
                __nv_bfloat162 h0 = __floats2bfloat162_rn(f00, f01);
                __nv_bfloat162 h1 = __floats2bfloat162_rn(f10, f11);
                __nv_bfloat162 l0 = __floats2bfloat162_rn(
                    f00 - __bfloat162float(h0.x), f01 - __bfloat162float(h0.y));
                __nv_bfloat162 l1 = __floats2bfloat162_rn(
                    f10 - __bfloat162float(h1.x), f11 - __bfloat162float(h1.y));
                size_t o0 = e * oES + (size_t)gr0 * HIDC + gc;
                size_t o1 = e * oES + (size_t)gr1 * HIDC + gc;
                *(__nv_bfloat162*)(OutHi + o0) = h0;
                *(__nv_bfloat162*)(OutHi + o1) = h1;
                *(__nv_bfloat162*)(OutLo + o0) = l0;
                *(__nv_bfloat162*)(OutLo + o1) = l1;
            } else {
                size_t o0 = e * oES + (size_t)gr0 * HIDC + gc;
                size_t o1 = e * oES + (size_t)gr1 * HIDC + gc;
                *(float2*)(OutF + o0) = make_float2(f00, f01);
                *(float2*)(OutF + o1) = make_float2(f10, f11);
            }
        }
    }
    #undef ISSUE
}

// ---------------- Gram-Schmidt + gather (reads compacted O via pos) ---------
template <int M>
__device__ __forceinline__ void blockReduce(float* vals, float (*red)[8], int tid)
{
    int lane = tid & 31, w = tid >> 5;
    #pragma unroll
    for (int i = 0; i < M; i++) {
        float v = vals[i];
        #pragma unroll
        for (int o = 16; o; o >>= 1) v += __shfl_xor_sync(0xffffffffu, v, o);
        if (lane == 0) red[i][w] = v;
    }
    __syncthreads();
    #pragma unroll
    for (int i = 0; i < M; i++) {
        float s = 0.f;
        #pragma unroll
        for (int ww = 0; ww < 8; ww++) s += red[i][ww];
        vals[i] = s;
    }
    __syncthreads();
}

__global__ void gs_kernel(const float* __restrict__ O,
                          const float* __restrict__ gate,
                          const int*   __restrict__ idx,
                          const int*   __restrict__ pos,
                          float* __restrict__ out)
{
    __shared__ float red[3][8];
    int n   = blockIdx.x;
    int tid = threadIdx.x;
    int kmax = idx[n];
    float g  = gate[n];
    const size_t NH = (size_t)N_TOK * HIDC;
    const float* base = O + (size_t)pos[n] * HIDC + tid * 8;

    float b[4][8];
    float t[8], w[8];

    #pragma unroll
    for (int i = 0; i < 4; i++) {
        if (i > kmax) break;
        float4 p0 = *(const float4*)(base + (size_t)i * NH);
        float4 p1 = *(const float4*)(base + (size_t)i * NH + 4);
        t[0]=p0.x; t[1]=p0.y; t[2]=p0.z; t[3]=p0.w;
        t[4]=p1.x; t[5]=p1.y; t[6]=p1.z; t[7]=p1.w;

        float c[3] = {0.f, 0.f, 0.f};
        if (i > 0) {
            #pragma unroll
            for (int j = 0; j < 3; j++) {
                if (j < i) {
                    float d = 0.f;
                    #pragma unroll
                    for (int q = 0; q < 8; q++) d += t[q] * b[j][q];
                    c[j] = d;
                }
            }
            blockReduce<3>(c, red, tid);
        }
        float ss[1] = {0.f};
        #pragma unroll
        for (int q = 0; q < 8; q++) {
            float wv = t[q];
            #pragma unroll
            for (int j = 0; j < 3; j++) if (j < i) wv -= c[j] * b[j][q];
            w[q] = wv;
            ss[0] += wv * wv;
        }
        blockReduce<1>(ss, red, tid);
        float inv = rsqrtf(ss[0]);
        #pragma unroll
        for (int q = 0; q < 8; q++) b[i][q] = w[q] * inv;

        if (i == kmax) {
            float4 o0, o1;
            o0.x = g * b[i][0]; o0.y = g * b[i][1];
            o0.z = g * b[i][2]; o0.w = g * b[i][3];
            o1.x = g * b[i][4]; o1.y = g * b[i][5];
            o1.z = g * b[i][6]; o1.w = g * b[i][7];
            float* op = out + (size_t)n * HIDC + tid * 8;
            *(float4*)(op)     = o0;
            *(float4*)(op + 4) = o1;
        }
    }
}

// ---------------------------------------------------------------------------
extern "C" void kernel_launch(void* const* d_in, const int* in_sizes, int n_in,
                              void* d_out, int out_size)
{
    const float* X    = (const float*)d_in[0];
    const int*   task = (const int*)  d_in[1];
    const float* temb = (const float*)d_in[2];
    const float* rmat = (const float*)d_in[3];
    const float* W1   = (const float*)d_in[4];
    const float* b1   = (const float*)d_in[5];
    const float* W2   = (const float*)d_in[6];
    const float* b2   = (const float*)d_in[7];
    float* out = (float*)d_out;

    bf16 *Xhi, *Xlo, *W1Thi, *W1Tlo, *W2Thi, *W2Tlo, *Hhi, *Hlo;
    float *O, *gate;
    int *idx, *pos, *perm, *cnt, *off, *start, *cntge;
    cudaGetSymbolAddress((void**)&Xhi,   g_Xhi);
    cudaGetSymbolAddress((void**)&Xlo,   g_Xlo);
    cudaGetSymbolAddress((void**)&W1Thi, g_W1Thi);
    cudaGetSymbolAddress((void**)&W1Tlo, g_W1Tlo);
    cudaGetSymbolAddress((void**)&W2Thi, g_W2Thi);
    cudaGetSymbolAddress((void**)&W2Tlo, g_W2Tlo);
    cudaGetSymbolAddress((void**)&Hhi,   g_Hhi);
    cudaGetSymbolAddress((void**)&Hlo,   g_Hlo);
    cudaGetSymbolAddress((void**)&O,     g_O);
    cudaGetSymbolAddress((void**)&gate,  g_gate);
    cudaGetSymbolAddress((void**)&idx,   g_idx);
    cudaGetSymbolAddress((void**)&pos,   g_pos);
    cudaGetSymbolAddress((void**)&perm,  g_perm);
    cudaGetSymbolAddress((void**)&cnt,   g_cnt);
    cudaGetSymbolAddress((void**)&off,   g_off);
    cudaGetSymbolAddress((void**)&start, g_start);
    cudaGetSymbolAddress((void**)&cntge, g_cntge);

    cudaFuncSetAttribute(gemm_hmma, cudaFuncAttributeMaxDynamicSharedMemorySize,
                         GEMM_SMEM);

    // router -> gate/idx/reg_loss
    router_kernel<<<N_TOK / 8, 256>>>(X, task, temb, rmat, gate, idx,
                                      out + (size_t)N_TOK * HIDC);

    // compaction: sort tokens by idx descending (counting sort)
    init_cnt_kernel<<<1, 32>>>(cnt, off);
    hist_kernel<<<N_TOK / 256, 256>>>(idx, cnt);
    scan_kernel<<<1, 32>>>(cnt, start, cntge);
    pos_kernel<<<N_TOK / 256, 256>>>(idx, start, off, pos, perm);

    // preps
    gather_split_kernel<<<(N_TOK * IN_DIMC / 4 + 255) / 256, 256>>>(
        X, perm, Xhi, Xlo);
    transpose_split<<<dim3(HIDC/32, IN_DIMC/32, NE), dim3(32, 8)>>>(
        W1, W1Thi, W1Tlo, IN_DIMC, HIDC);
    transpose_split<<<dim3(HIDC/32, HIDC/32, NE), dim3(32, 8)>>>(
        W2, W2Thi, W2Tlo, HIDC, HIDC);

    dim3 gg(HIDC / 128, N_TOK / 128, NE);
    // GEMM1: H = relu(Xs @ W1 + b1) -> bf16 hi/lo (compacted rows)
    gemm_hmma<<<gg, 256, GEMM_SMEM>>>(
        Xhi, Xlo, W1Thi, W1Tlo, b1, Hhi, Hlo, nullptr, cntge,
        IN_DIMC, 0,
        (size_t)0, (size_t)HIDC * IN_DIMC, (size_t)HIDC, (size_t)N_TOK * HIDC);
    // GEMM2: O = relu(H @ W2 + b2) -> f32 (compacted rows)
    gemm_hmma<<<gg, 256, GEMM_SMEM>>>(
        Hhi, Hlo, W2Thi, W2Tlo, b2, nullptr, nullptr, O, cntge,
        HIDC, 1,
        (size_t)N_TOK * HIDC, (size_t)HIDC * HIDC, (size_t)HIDC, (size_t)N_TOK * HIDC);

    gs_kernel<<<N_TOK, 256>>>(O, gate, idx, pos, out);
}

// round 16
// speedup vs baseline: 3.5585x; 1.0060x over previous
#include <cuda_runtime.h>
#include <cuda_bf16.h>
#include <cstdint>
#include <cstddef>

#define N_TOK   8192
#define IN_DIMC 1024
#define HIDC    2048
#define NE      4
#define TEDC    100
#define MU_C    0.01f
#define EPS_C   1e-6f

typedef __nv_bfloat16 bf16;

// ---------------- scratch (__device__ globals; no allocations) --------------
__device__ bf16  g_Xhi [(size_t)N_TOK * IN_DIMC];        // compacted rows
__device__ bf16  g_Xlo [(size_t)N_TOK * IN_DIMC];
__device__ bf16  g_W1Thi[(size_t)NE * HIDC * IN_DIMC];   // [e][n][k]
__device__ bf16  g_W1Tlo[(size_t)NE * HIDC * IN_DIMC];
__device__ bf16  g_W2Thi[(size_t)NE * HIDC * HIDC];      // [e][n][k]
__device__ bf16  g_W2Tlo[(size_t)NE * HIDC * HIDC];
__device__ bf16  g_Hhi [(size_t)NE * N_TOK * HIDC];      // compacted rows
__device__ bf16  g_Hlo [(size_t)NE * N_TOK * HIDC];
__device__ float g_O   [(size_t)NE * N_TOK * HIDC];      // compacted rows
__device__ float g_gate[N_TOK];
__device__ int   g_idx [N_TOK];
__device__ int   g_pos [N_TOK];          // token -> compacted position
__device__ int   g_perm[N_TOK];          // compacted position -> token
__device__ int   g_cntge[NE];            // #tokens with idx >= e

// ---------------- PTX helpers ------------------------------------------------
__device__ __forceinline__ uint32_t smem_u32(const void* p) {
    uint32_t a;
    asm("{ .reg .u64 t; cvta.to.shared.u64 t, %1; cvt.u32.u64 %0, t; }"
        : "=r"(a) : "l"(p));
    return a;
}
#define CPASYNC16(s, g) \
    asm volatile("cp.async.cg.shared.global [%0], [%1], 16;" \
                 :: "r"(s), "l"(g) : "memory")
#define CP_COMMIT() asm volatile("cp.async.commit_group;" ::: "memory")
#define CP_WAIT(n)  asm volatile("cp.async.wait_group %0;" :: "n"(n) : "memory")
#define LDMX4(R, addr) \
    asm volatile("ldmatrix.sync.aligned.m8n8.x4.shared.b16 {%0,%1,%2,%3}, [%4];" \
                 : "=r"((R)[0]), "=r"((R)[1]), "=r"((R)[2]), "=r"((R)[3]) \
                 : "r"(addr))
#define MMA16816(C, A, B) \
    asm volatile("mma.sync.aligned.m16n8k16.row.col.f32.bf16.bf16.f32 " \
                 "{%0,%1,%2,%3},{%4,%5,%6,%7},{%8,%9},{%0,%1,%2,%3};" \
                 : "+f"((C)[0]), "+f"((C)[1]), "+f"((C)[2]), "+f"((C)[3]) \
                 : "r"((A)[0]), "r"((A)[1]), "r"((A)[2]), "r"((A)[3]), \
                   "r"((B)[0]), "r"((B)[1]))

// [128 rows][4 data chunks of 16B] staged with row stride of FIVE chunks.
// chunk = r*5 + c; 5 is invertible mod 8 => 8 consecutive rows at fixed c
// hit 8 distinct 16B bank groups: conflict-free ldmatrix and STS.
// (hardware-proven configuration from the measured-passing R10 kernel)
__device__ __forceinline__ uint32_t swz(int r, int c) {
    return (uint32_t)((r * 5 + c) * 16);
}

// ---------------- router -----------------------------------------------------
__global__ void router_kernel(const float* __restrict__ X,
                              const int*   __restrict__ task,
                              const float* __restrict__ temb,
                              const float* __restrict__ rmat,
                              float* __restrict__ gate,
                              int*   __restrict__ idxOut,
                              float* __restrict__ regLoss)
{
    int warp = (blockIdx.x * blockDim.x + threadIdx.x) >> 5;
    int lane = threadIdx.x & 31;
    if (warp >= N_TOK) return;

    const float* x  = X + (size_t)warp * IN_DIMC;
    const float* te = temb + (size_t)task[warp] * TEDC;
    const float4* r4 = (const float4*)rmat;

    float a0 = 0.f, a1 = 0.f, a2 = 0.f, a3 = 0.f;
    for (int k = lane; k < IN_DIMC; k += 32) {
        float xv = x[k]; float4 r = r4[k];
        a0 += xv * r.x; a1 += xv * r.y; a2 += xv * r.z; a3 += xv * r.w;
    }
    for (int k = lane; k < TEDC; k += 32) {
        float xv = te[k]; float4 r = r4[IN_DIMC + k];
        a0 += xv * r.x; a1 += xv * r.y; a2 += xv * r.z; a3 += xv * r.w;
    }
    #pragma unroll
    for (int o = 16; o; o >>= 1) {
        a0 += __shfl_xor_sync(0xffffffffu, a0, o);
        a1 += __shfl_xor_sync(0xffffffffu, a1, o);
        a2 += __shfl_xor_sync(0xffffffffu, a2, o);
        a3 += __shfl_xor_sync(0xffffffffu, a3, o);
    }
    if (lane == 0) {
        float l[4] = {a0, a1, a2, a3};
        int best = 0; float bm = l[0];
        #pragma unroll
        for (int e = 1; e < 4; e++) if (l[e] > bm) { bm = l[e]; best = e; }
        float s = 0.f;
        #pragma unroll
        for (int e = 0; e < 4; e++) s += expf(l[e] - bm);
        float g = 1.0f / s;
        gate[warp]   = g;
        idxOut[warp] = best;
        regLoss[warp] = -(MU_C / (float)NE) * (logf(g + EPS_C) + 3.0f * logf(EPS_C));
    }
}

// ---------------- compaction: single-block counting sort ---------------------
// Order within a bucket is nondeterministic but provably irrelevant: outputs
// are indexed by original token id, and every consumer only needs the prefix
// property p < cntge[e] for e <= idx (descending-idx buckets give that).
__global__ void compact_kernel(const int* __restrict__ idx,
                               int* __restrict__ pos, int* __restrict__ perm,
                               int* __restrict__ cntge)
{
    __shared__ int scnt[NE], scur[NE];
    int tid = threadIdx.x;                 // 1024 threads
    if (tid < NE) scnt[tid] = 0;
    __syncthreads();
    for (int n = tid; n < N_TOK; n += 1024) atomicAdd(&scnt[idx[n]], 1);
    __syncthreads();
    if (tid == 0) {
        int s = 0;
        #pragma unroll
        for (int e = NE - 1; e >= 0; e--) { scur[e] = s; s += scnt[e]; }
        #pragma unroll
        for (int e = 0; e < NE; e++) cntge[e] = scur[e] + scnt[e];
    }
    __syncthreads();
    for (int n = tid; n < N_TOK; n += 1024) {
        int e = idx[n];
        int p = atomicAdd(&scur[e], 1);
        pos[n] = p;
        perm[p] = n;
    }
}

// ---------------- fused prep: gather+split X, transpose+split W1, W2 --------
// Region decode by blockIdx.x:
//   [0, 8192)          gather_split of X (permuted rows) -> Xhi/Xlo
//   [8192, 16384)      W1 [e][K=1024][N=2048] -> [e][N][K] hi/lo
//   [16384, 32768)     W2 [e][K=2048][N=2048] -> [e][N][K] hi/lo
__global__ void prep_kernel(const float* __restrict__ X,
                            const int* __restrict__ perm,
                            bf16* __restrict__ Xhi, bf16* __restrict__ Xlo,
                            const float* __restrict__ W1,
                            bf16* __restrict__ W1hi, bf16* __restrict__ W1lo,
                            const float* __restrict__ W2,
                            bf16* __restrict__ W2hi, bf16* __restrict__ W2lo)
{
    __shared__ float tile[32][33];
    int b   = blockIdx.x;
    int tid = threadIdx.x;

    if (b < 8192) {
        // gather + split: one float4 per thread
        size_t i = (size_t)b * 256 + tid;          // float4 index
        int row = (int)(i >> 8);                    // IN_DIMC/4 = 256
        int c4  = (int)(i & 255);
        int src = perm[row];
        float4 v = *(const float4*)(X + (size_t)src * IN_DIMC + c4 * 4);
        float f[4] = {v.x, v.y, v.z, v.w};
        union { unsigned short u[4]; uint2 q; } H, L;
        #pragma unroll
        for (int j = 0; j < 4; j++) {
            bf16 h = __float2bfloat16(f[j]);
            bf16 l = __float2bfloat16(f[j] - __bfloat162float(h));
            H.u[j] = __bfloat16_as_ushort(h);
            L.u[j] = __bfloat16_as_ushort(l);
        }
        ((uint2*)Xhi)[i] = H.q;
        ((uint2*)Xlo)[i] = L.q;
        return;
    }

    // transpose + split path
    const float* W; bf16* Thi; bf16* Tlo;
    int K, N, e, k0, n0;
    if (b < 16384) {
        int bb = b - 8192;                 // 4 * 32 * 64 = 8192 blocks
        W = W1; Thi = W1hi; Tlo = W1lo; K = IN_DIMC; N = HIDC;
        e  = bb >> 11;                     // 2048 blocks per expert
        int rem = bb & 2047;
        k0 = (rem >> 6) * 32;              // 32 k-tiles
        n0 = (rem & 63) * 32;              // 64 n-tiles
    } else {
        int bb = b - 16384;                // 4 * 64 * 64 = 16384 blocks
        W = W2; Thi = W2hi; Tlo = W2lo; K = HIDC; N = HIDC;
        e  = bb >> 12;                     // 4096 blocks per expert
        int rem = bb & 4095;
        k0 = (rem >> 6) * 32;              // 64 k-tiles
        n0 = (rem & 63) * 32;              // 64 n-tiles
    }
    int tx = tid & 31, ty = tid >> 5;      // (32, 8)
    const float* We = W + (size_t)e * K * N;
    for (int r = ty; r < 32; r += 8)
        tile[r][tx] = We[(size_t)(k0 + r) * N + n0 + tx];
    __syncthreads();
    size_t ebase = (size_t)e * K * N;
    for (int r = ty; r < 32; r += 8) {
        float v = tile[tx][r];
        bf16 h = __float2bfloat16(v);
        bf16 l = __float2bfloat16(v - __bfloat162float(h));
        size_t o = ebase + (size_t)(n0 + r) * K + k0 + tx;
        Thi[o] = h; Tlo[o] = l;
    }
}

// ---------------------------------------------------------------------------
// HMMA bf16 3-pass GEMM: D[m][n] = sum_k A[m][k]*B[n][k], A=Ahi+Alo, B=Bhi+Blo
// (hh + hl + lh passes, shared fp32 accumulators). CTA tile 128x128, BK=32.
// 8 warps as 2(m) x 4(n); warp tile 64x32. cp.async 3-stage pipeline.
// mode 0: out = relu(D+bias) -> bf16 hi/lo; mode 1: -> f32.
// CTAs with m0 >= cntge[e] exit immediately (expert skipping).
// Hardware-proven configuration (R10 measured PASS, 2324.6 us, 7.8e-6).
// ---------------------------------------------------------------------------
#define TILEB  10240         // [128 rows][5 chunks x 16B] (4 data + 1 pad)
#define STAGEB (4 * TILEB)   // Ahi Alo Bhi Blo
#define NSTAGE 3
#define GEMM_SMEM (NSTAGE * STAGEB)   // 122880

__global__ __launch_bounds__(256, 1)
void gemm_hmma(const bf16* __restrict__ Ahi, const bf16* __restrict__ Alo,
               const bf16* __restrict__ Bhi, const bf16* __restrict__ Blo,
               const float* __restrict__ bias,
               bf16* __restrict__ OutHi, bf16* __restrict__ OutLo,
               float* __restrict__ OutF,
               const int* __restrict__ cntge,
               int K, int mode,
               size_t aES, size_t bES, size_t biasES, size_t oES)
{
    int e  = blockIdx.z;
    int m0 = blockIdx.y * 128;
    if (m0 >= cntge[e]) return;        // expert skipping
    int n0 = blockIdx.x * 128;

    extern __shared__ __align__(128) char smem[];
    uint32_t sbase = smem_u32(smem);

    int tid  = threadIdx.x;
    int wid  = tid >> 5, lane = tid & 31;
    int wm0  = (wid & 1) * 64;
    int wn0  = (wid >> 1) * 32;

    const bf16* gAh = Ahi + e * aES + (size_t)m0 * K;
    const bf16* gAl = Alo + e * aES + (size_t)m0 * K;
    const bf16* gBh = Bhi + e * bES + (size_t)n0 * K;
    const bf16* gBl = Blo + e * bES + (size_t)n0 * K;

    int nT = K >> 5;                   // BK = 32

    // accumulators: 4 m-tiles x 4 n-tiles x 4 regs
    float acc[4][4][4];
    #pragma unroll
    for (int i = 0; i < 4; i++)
        #pragma unroll
        for (int j = 0; j < 4; j++)
            #pragma unroll
            for (int q = 0; q < 4; q++) acc[i][j][q] = 0.f;

    // loader: thread covers data chunks 2*tid, 2*tid+1 of each 512-chunk tile
    int j0 = tid * 2;

    #define ISSUE(t)                                                         \
        do {                                                                 \
            if ((t) < nT) {                                                  \
                uint32_t sb_ = sbase + ((t) % NSTAGE) * STAGEB;              \
                _Pragma("unroll")                                            \
                for (int q_ = 0; q_ < 2; q_++) {                             \
                    int j_ = j0 + q_;                                        \
                    int r_ = j_ >> 2, c_ = j_ & 3;                           \
                    uint32_t so_ = swz(r_, c_);                              \
                    size_t go_ = (size_t)r_ * K + (size_t)(t) * 32 + c_ * 8; \
                    CPASYNC16(sb_ + 0 * TILEB + so_, gAh + go_);             \
                    CPASYNC16(sb_ + 1 * TILEB + so_, gAl + go_);             \
                    CPASYNC16(sb_ + 2 * TILEB + so_, gBh + go_);             \
                    CPASYNC16(sb_ + 3 * TILEB + so_, gBl + go_);             \
                }                                                            \
            }                                                                \
            CP_COMMIT();                                                     \
        } while (0)

    ISSUE(0);
    ISSUE(1);

    for (int t = 0; t < nT; t++) {
        CP_WAIT(1);            // stage t complete (only t+1 may be pending)
        __syncthreads();       // also orders prior compute before next ISSUE

        uint32_t sb  = sbase + (t % NSTAGE) * STAGEB;
        uint32_t sAh = sb, sAl = sb + TILEB, sBh = sb + 2 * TILEB, sBl = sb + 3 * TILEB;

        #pragma unroll
        for (int ks = 0; ks < 2; ks++) {
            int kc = ks * 2;
            uint32_t Ah[4][4], Al[4][4], Bh[2][4], Bl[2][4];
            #pragma unroll
            for (int mi = 0; mi < 4; mi++) {
                int row = wm0 + mi * 16 + (lane & 15);
                int c   = kc + (lane >> 4);
                uint32_t off = swz(row, c);
                LDMX4(Ah[mi], sAh + off);
                LDMX4(Al[mi], sAl + off);
            }
            #pragma unroll
            for (int bi = 0; bi < 2; bi++) {
                int row = wn0 + bi * 16 + ((lane >> 4) & 1) * 8 + (lane & 7);
                int c   = kc + ((lane >> 3) & 1);
                uint32_t off = swz(row, c);
                LDMX4(Bh[bi], sBh + off);
                LDMX4(Bl[bi], sBl + off);
            }
            #pragma unroll
            for (int mi = 0; mi < 4; mi++) {
                #pragma unroll
                for (int ni = 0; ni < 4; ni++) {
                    uint32_t* bh = &Bh[ni >> 1][(ni & 1) * 2];
                    uint32_t* bl = &Bl[ni >> 1][(ni & 1) * 2];
                    MMA16816(acc[mi][ni], Ah[mi], bh);   // hi*hi
                    MMA16816(acc[mi][ni], Ah[mi], bl);   // hi*lo
                    MMA16816(acc[mi][ni], Al[mi], bh);   // lo*hi
                }
            }
        }
        ISSUE(t + 2);
    }

    // epilogue
    const float* biasE = bias + e * biasES;
    #pragma unroll
    for (int mi = 0; mi < 4; mi++) {
        #pragma unroll
        for (int ni = 0; ni < 4; ni++) {
            int gr0 = m0 + wm0 + mi * 16 + (lane >> 2);
            int gr1 = gr0 + 8;
            int gc  = n0 + wn0 + ni * 8 + (lane & 3) * 2;
            float bv0 = __ldg(biasE + gc), bv1 = __ldg(biasE + gc + 1);
            float f00 = fmaxf(acc[mi][ni][0] + bv0, 0.f);
            float f01 = fmaxf(acc[mi][ni][1] + bv1, 0.f);
            float f10 = fmaxf(acc[mi][ni][2] + bv0, 0.f);
            float f11 = fmaxf(acc[mi][ni][3] + bv1, 0.f);
            if (mode == 0) {
                __nv_bfloat162 h0 = __floats2bfloat162_rn(f00, f01);
                __nv_bfloat162 h1 = __floats2bfloat162_rn(f10, f11);
                __nv_bfloat162 l0 = __floats2bfloat162_rn(
                    f00 - __bfloat162float(h0.x), f01 - __bfloat162float(h0.y));
                __nv_bfloat162 l1 = __floats2bfloat162_rn(
                    f10 - __bfloat162float(h1.x), f11 - __bfloat162float(h1.y));
                size_t o0 = e * oES + (size_t)gr0 * HIDC + gc;
                size_t o1 = e * oES + (size_t)gr1 * HIDC + gc;
                *(__nv_bfloat162*)(OutHi + o0) = h0;
                *(__nv_bfloat162*)(OutHi + o1) = h1;
                *(__nv_bfloat162*)(OutLo + o0) = l0;
                *(__nv_bfloat162*)(OutLo + o1) = l1;
            } else {
                size_t o0 = e * oES + (size_t)gr0 * HIDC + gc;
                size_t o1 = e * oES + (size_t)gr1 * HIDC + gc;
                *(float2*)(OutF + o0) = make_float2(f00, f01);
                *(float2*)(OutF + o1) = make_float2(f10, f11);
            }
        }
    }
    #undef ISSUE
}

// ---------------- Gram-Schmidt + gather (reads compacted O via pos) ---------
template <int M>
__device__ __forceinline__ void blockReduce(float* vals, float (*red)[8], int tid)
{
    int lane = tid & 31, w = tid >> 5;
    #pragma unroll
    for (int i = 0; i < M; i++) {
        float v = vals[i];
        #pragma unroll
        for (int o = 16; o; o >>= 1) v += __shfl_xor_sync(0xffffffffu, v, o);
        if (lane == 0) red[i][w] = v;
    }
    __syncthreads();
    #pragma unroll
    for (int i = 0; i < M; i++) {
        float s = 0.f;
        #pragma unroll
        for (int ww = 0; ww < 8; ww++) s += red[i][ww];
        vals[i] = s;
    }
    __syncthreads();
}

__global__ void gs_kernel(const float* __restrict__ O,
                          const float* __restrict__ gate,
                          const int*   __restrict__ idx,
                          const int*   __restrict__ pos,
                          float* __restrict__ out)
{
    __shared__ float red[3][8];
    int n   = blockIdx.x;
    int tid = threadIdx.x;
    int kmax = idx[n];
    float g  = gate[n];
    const size_t NH = (size_t)N_TOK * HIDC;
    const float* base = O + (size_t)pos[n] * HIDC + tid * 8;

    float b[4][8];
    float t[8], w[8];

    #pragma unroll
    for (int i = 0; i < 4; i++) {
        if (i > kmax) break;
        float4 p0 = *(const float4*)(base + (size_t)i * NH);
        float4 p1 = *(const float4*)(base + (size_t)i * NH + 4);
        t[0]=p0.x; t[1]=p0.y; t[2]=p0.z; t[3]=p0.w;
        t[4]=p1.x; t[5]=p1.y; t[6]=p1.z; t[7]=p1.w;

        float c[3] = {0.f, 0.f, 0.f};
        if (i > 0) {
            #pragma unroll
            for (int j = 0; j < 3; j++) {
                if (j < i) {
                    float d = 0.f;
                    #pragma unroll
                    for (int q = 0; q < 8; q++) d += t[q] * b[j][q];
                    c[j] = d;
                }
            }
            blockReduce<3>(c, red, tid);
        }
        float ss[1] = {0.f};
        #pragma unroll
        for (int q = 0; q < 8; q++) {
            float wv = t[q];
            #pragma unroll
            for (int j = 0; j < 3; j++) if (j < i) wv -= c[j] * b[j][q];
            w[q] = wv;
            ss[0] += wv * wv;
        }
        blockReduce<1>(ss, red, tid);
        float inv = rsqrtf(ss[0]);
        #pragma unroll
        for (int q = 0; q < 8; q++) b[i][q] = w[q] * inv;

        if (i == kmax) {
            float4 o0, o1;
            o0.x = g * b[i][0]; o0.y = g * b[i][1];
            o0.z = g * b[i][2]; o0.w = g * b[i][3];
            o1.x = g * b[i][4]; o1.y = g * b[i][5];
            o1.z = g * b[i][6]; o1.w = g * b[i][7];
            float* op = out + (size_t)n * HIDC + tid * 8;
            *(float4*)(op)     = o0;
            *(float4*)(op + 4) = o1;
        }
    }
}

// ---------------------------------------------------------------------------
extern "C" void kernel_launch(void* const* d_in, const int* in_sizes, int n_in,
                              void* d_out, int out_size)
{
    const float* X    = (const float*)d_in[0];
    const int*   task = (const int*)  d_in[1];
    const float* temb = (const float*)d_in[2];
    const float* rmat = (const float*)d_in[3];
    const float* W1   = (const float*)d_in[4];
    const float* b1   = (const float*)d_in[5];
    const float* W2   = (const float*)d_in[6];
    const float* b2   = (const float*)d_in[7];
    float* out = (float*)d_out;

    bf16 *Xhi, *Xlo, *W1Thi, *W1Tlo, *W2Thi, *W2Tlo, *Hhi, *Hlo;
    float *O, *gate;
    int *idx, *pos, *perm, *cntge;
    cudaGetSymbolAddress((void**)&Xhi,   g_Xhi);
    cudaGetSymbolAddress((void**)&Xlo,   g_Xlo);
    cudaGetSymbolAddress((void**)&W1Thi, g_W1Thi);
    cudaGetSymbolAddress((void**)&W1Tlo, g_W1Tlo);
    cudaGetSymbolAddress((void**)&W2Thi, g_W2Thi);
    cudaGetSymbolAddress((void**)&W2Tlo, g_W2Tlo);
    cudaGetSymbolAddress((void**)&Hhi,   g_Hhi);
    cudaGetSymbolAddress((void**)&Hlo,   g_Hlo);
    cudaGetSymbolAddress((void**)&O,     g_O);
    cudaGetSymbolAddress((void**)&gate,  g_gate);
    cudaGetSymbolAddress((void**)&idx,   g_idx);
    cudaGetSymbolAddress((void**)&pos,   g_pos);
    cudaGetSymbolAddress((void**)&perm,  g_perm);
    cudaGetSymbolAddress((void**)&cntge, g_cntge);

    cudaFuncSetAttribute(gemm_hmma, cudaFuncAttributeMaxDynamicSharedMemorySize,
                         GEMM_SMEM);

    // 1) router -> gate/idx/reg_loss
    router_kernel<<<N_TOK / 8, 256>>>(X, task, temb, rmat, gate, idx,
                                      out + (size_t)N_TOK * HIDC);

    // 2) compaction (single block counting sort, descending idx)
    compact_kernel<<<1, 1024>>>(idx, pos, perm, cntge);

    // 3) fused preps: gather/split X + transpose/split W1, W2
    prep_kernel<<<32768, 256>>>(X, perm, Xhi, Xlo,
                                W1, W1Thi, W1Tlo,
                                W2, W2Thi, W2Tlo);

    dim3 gg(HIDC / 128, N_TOK / 128, NE);
    // 4) GEMM1: H = relu(Xs @ W1 + b1) -> bf16 hi/lo   [profiled slot]
    gemm_hmma<<<gg, 256, GEMM_SMEM>>>(
        Xhi, Xlo, W1Thi, W1Tlo, b1, Hhi, Hlo, nullptr, cntge,
        IN_DIMC, 0,
        (size_t)0, (size_t)HIDC * IN_DIMC, (size_t)HIDC, (size_t)N_TOK * HIDC);
    // 5) GEMM2: O = relu(H @ W2 + b2) -> f32
    gemm_hmma<<<gg, 256, GEMM_SMEM>>>(
        Hhi, Hlo, W2Thi, W2Tlo, b2, nullptr, nullptr, O, cntge,
        HIDC, 1,
        (size_t)N_TOK * HIDC, (size_t)HIDC * HIDC, (size_t)HIDC, (size_t)N_TOK * HIDC);

    // 6) Gram-Schmidt + gather
    gs_kernel<<<N_TOK, 256>>>(O, gate, idx, pos, out);
}

// round 17
// speedup vs baseline: 3.5999x; 1.0116x over previous
#include <cuda_runtime.h>
#include <cuda_bf16.h>
#include <cstdint>
#include <cstddef>

#define N_TOK   8192
#define IN_DIMC 1024
#define HIDC    2048
#define NE      4
#define TEDC    100
#define MU_C    0.01f
#define EPS_C   1e-6f

typedef __nv_bfloat16 bf16;

// ---------------- scratch (__device__ globals; no allocations) --------------
__device__ bf16  g_Xhi [(size_t)N_TOK * IN_DIMC];        // compacted rows
__device__ bf16  g_Xlo [(size_t)N_TOK * IN_DIMC];
__device__ bf16  g_W1Thi[(size_t)NE * HIDC * IN_DIMC];   // [e][n][k]
__device__ bf16  g_W1Tlo[(size_t)NE * HIDC * IN_DIMC];
__device__ bf16  g_W2Thi[(size_t)NE * HIDC * HIDC];      // [e][n][k]
__device__ bf16  g_W2Tlo[(size_t)NE * HIDC * HIDC];
__device__ bf16  g_Hhi [(size_t)NE * N_TOK * HIDC];      // compacted rows
__device__ bf16  g_Hlo [(size_t)NE * N_TOK * HIDC];
__device__ float g_O   [(size_t)NE * N_TOK * HIDC];      // compacted rows
__device__ float g_gate[N_TOK];
__device__ int   g_idx [N_TOK];
__device__ int   g_pos [N_TOK];          // token -> compacted position
__device__ int   g_perm[N_TOK];          // compacted position -> token
__device__ int   g_cntge[NE];            // #tokens with idx >= e

// ---------------- PTX helpers ------------------------------------------------
__device__ __forceinline__ uint32_t smem_u32(const void* p) {
    uint32_t a;
    asm("{ .reg .u64 t; cvta.to.shared.u64 t, %1; cvt.u32.u64 %0, t; }"
        : "=r"(a) : "l"(p));
    return a;
}
#define CPASYNC16(s, g) \
    asm volatile("cp.async.cg.shared.global [%0], [%1], 16;" \
                 :: "r"(s), "l"(g) : "memory")
#define CP_COMMIT() asm volatile("cp.async.commit_group;" ::: "memory")
#define CP_WAIT(n)  asm volatile("cp.async.wait_group %0;" :: "n"(n) : "memory")
#define LDMX4(R, addr) \
    asm volatile("ldmatrix.sync.aligned.m8n8.x4.shared.b16 {%0,%1,%2,%3}, [%4];" \
                 : "=r"((R)[0]), "=r"((R)[1]), "=r"((R)[2]), "=r"((R)[3]) \
                 : "r"(addr))
#define MMA16816(C, A, B) \
    asm volatile("mma.sync.aligned.m16n8k16.row.col.f32.bf16.bf16.f32 " \
                 "{%0,%1,%2,%3},{%4,%5,%6,%7},{%8,%9},{%0,%1,%2,%3};" \
                 : "+f"((C)[0]), "+f"((C)[1]), "+f"((C)[2]), "+f"((C)[3]) \
                 : "r"((A)[0]), "r"((A)[1]), "r"((A)[2]), "r"((A)[3]), \
                   "r"((B)[0]), "r"((B)[1]))

// [128 rows][4 data chunks of 16B] staged with row stride of FIVE chunks.
// chunk = r*5 + c; 5 is invertible mod 8 => 8 consecutive rows at fixed c
// hit 8 distinct 16B bank groups: conflict-free ldmatrix and STS.
// (hardware-proven configuration from the measured-passing R10/R16 kernels)
__device__ __forceinline__ uint32_t swz(int r, int c) {
    return (uint32_t)((r * 5 + c) * 16);
}

// ---------------- router -----------------------------------------------------
__global__ void router_kernel(const float* __restrict__ X,
                              const int*   __restrict__ task,
                              const float* __restrict__ temb,
                              const float* __restrict__ rmat,
                              float* __restrict__ gate,
                              int*   __restrict__ idxOut,
                              float* __restrict__ regLoss)
{
    int warp = (blockIdx.x * blockDim.x + threadIdx.x) >> 5;
    int lane = threadIdx.x & 31;
    if (warp >= N_TOK) return;

    const float* x  = X + (size_t)warp * IN_DIMC;
    const float* te = temb + (size_t)task[warp] * TEDC;
    const float4* r4 = (const float4*)rmat;

    float a0 = 0.f, a1 = 0.f, a2 = 0.f, a3 = 0.f;
    for (int k = lane; k < IN_DIMC; k += 32) {
        float xv = x[k]; float4 r = r4[k];
        a0 += xv * r.x; a1 += xv * r.y; a2 += xv * r.z; a3 += xv * r.w;
    }
    for (int k = lane; k < TEDC; k += 32) {
        float xv = te[k]; float4 r = r4[IN_DIMC + k];
        a0 += xv * r.x; a1 += xv * r.y; a2 += xv * r.z; a3 += xv * r.w;
    }
    #pragma unroll
    for (int o = 16; o; o >>= 1) {
        a0 += __shfl_xor_sync(0xffffffffu, a0, o);
        a1 += __shfl_xor_sync(0xffffffffu, a1, o);
        a2 += __shfl_xor_sync(0xffffffffu, a2, o);
        a3 += __shfl_xor_sync(0xffffffffu, a3, o);
    }
    if (lane == 0) {
        float l[4] = {a0, a1, a2, a3};
        int best = 0; float bm = l[0];
        #pragma unroll
        for (int e = 1; e < 4; e++) if (l[e] > bm) { bm = l[e]; best = e; }
        float s = 0.f;
        #pragma unroll
        for (int e = 0; e < 4; e++) s += expf(l[e] - bm);
        float g = 1.0f / s;
        gate[warp]   = g;
        idxOut[warp] = best;
        regLoss[warp] = -(MU_C / (float)NE) * (logf(g + EPS_C) + 3.0f * logf(EPS_C));
    }
}

// ---------------- compaction: single-block counting sort ---------------------
__global__ void compact_kernel(const int* __restrict__ idx,
                               int* __restrict__ pos, int* __restrict__ perm,
                               int* __restrict__ cntge)
{
    __shared__ int scnt[NE], scur[NE];
    int tid = threadIdx.x;                 // 1024 threads
    if (tid < NE) scnt[tid] = 0;
    __syncthreads();
    for (int n = tid; n < N_TOK; n += 1024) atomicAdd(&scnt[idx[n]], 1);
    __syncthreads();
    if (tid == 0) {
        int s = 0;
        #pragma unroll
        for (int e = NE - 1; e >= 0; e--) { scur[e] = s; s += scnt[e]; }
        #pragma unroll
        for (int e = 0; e < NE; e++) cntge[e] = scur[e] + scnt[e];
    }
    __syncthreads();
    for (int n = tid; n < N_TOK; n += 1024) {
        int e = idx[n];
        int p = atomicAdd(&scur[e], 1);
        pos[n] = p;
        perm[p] = n;
    }
}

// ---------------- fused prep: gather+split X, transpose+split W1, W2 --------
__global__ void prep_kernel(const float* __restrict__ X,
                            const int* __restrict__ perm,
                            bf16* __restrict__ Xhi, bf16* __restrict__ Xlo,
                            const float* __restrict__ W1,
                            bf16* __restrict__ W1hi, bf16* __restrict__ W1lo,
                            const float* __restrict__ W2,
                            bf16* __restrict__ W2hi, bf16* __restrict__ W2lo)
{
    __shared__ float tile[32][33];
    int b   = blockIdx.x;
    int tid = threadIdx.x;

    if (b < 8192) {
        size_t i = (size_t)b * 256 + tid;          // float4 index
        int row = (int)(i >> 8);                    // IN_DIMC/4 = 256
        int c4  = (int)(i & 255);
        int src = perm[row];
        float4 v = *(const float4*)(X + (size_t)src * IN_DIMC + c4 * 4);
        float f[4] = {v.x, v.y, v.z, v.w};
        union { unsigned short u[4]; uint2 q; } H, L;
        #pragma unroll
        for (int j = 0; j < 4; j++) {
            bf16 h = __float2bfloat16(f[j]);
            bf16 l = __float2bfloat16(f[j] - __bfloat162float(h));
            H.u[j] = __bfloat16_as_ushort(h);
            L.u[j] = __bfloat16_as_ushort(l);
        }
        ((uint2*)Xhi)[i] = H.q;
        ((uint2*)Xlo)[i] = L.q;
        return;
    }

    const float* W; bf16* Thi; bf16* Tlo;
    int K, N, e, k0, n0;
    if (b < 16384) {
        int bb = b - 8192;
        W = W1; Thi = W1hi; Tlo = W1lo; K = IN_DIMC; N = HIDC;
        e  = bb >> 11;
        int rem = bb & 2047;
        k0 = (rem >> 6) * 32;
        n0 = (rem & 63) * 32;
    } else {
        int bb = b - 16384;
        W = W2; Thi = W2hi; Tlo = W2lo; K = HIDC; N = HIDC;
        e  = bb >> 12;
        int rem = bb & 4095;
        k0 = (rem >> 6) * 32;
        n0 = (rem & 63) * 32;
    }
    int tx = tid & 31, ty = tid >> 5;
    const float* We = W + (size_t)e * K * N;
    for (int r = ty; r < 32; r += 8)
        tile[r][tx] = We[(size_t)(k0 + r) * N + n0 + tx];
    __syncthreads();
    size_t ebase = (size_t)e * K * N;
    for (int r = ty; r < 32; r += 8) {
        float v = tile[tx][r];
        bf16 h = __float2bfloat16(v);
        bf16 l = __float2bfloat16(v - __bfloat162float(h));
        size_t o = ebase + (size_t)(n0 + r) * K + k0 + tx;
        Thi[o] = h; Tlo[o] = l;
    }
}

// ---------------------------------------------------------------------------
// HMMA bf16 3-pass GEMM: D[m][n] = sum_k A[m][k]*B[n][k], A=Ahi+Alo, B=Bhi+Blo
// CTA tile 128x128, BK=32, 512 threads = 16 warps as 4(m) x 4(n), warp tile
// 32x32 (acc[2][4][4]). Smem layout identical to the measured-passing R16
// kernel; only the warp->tile mapping and thread count changed, raising
// occupancy from 2 to 4 warps/SMSP to cover LDSM latency + barrier tails.
// mode 0: out = relu(D+bias) -> bf16 hi/lo; mode 1: -> f32.
// ---------------------------------------------------------------------------
#define TILEB  10240         // [128 rows][5 chunks x 16B] (4 data + 1 pad)
#define STAGEB (4 * TILEB)   // Ahi Alo Bhi Blo
#define NSTAGE 3
#define GEMM_SMEM (NSTAGE * STAGEB)   // 122880

__global__ __launch_bounds__(512, 1)
void gemm_hmma(const bf16* __restrict__ Ahi, const bf16* __restrict__ Alo,
               const bf16* __restrict__ Bhi, const bf16* __restrict__ Blo,
               const float* __restrict__ bias,
               bf16* __restrict__ OutHi, bf16* __restrict__ OutLo,
               float* __restrict__ OutF,
               const int* __restrict__ cntge,
               int K, int mode,
               size_t aES, size_t bES, size_t biasES, size_t oES)
{
    int e  = blockIdx.z;
    int m0 = blockIdx.y * 128;
    if (m0 >= cntge[e]) return;        // expert skipping
    int n0 = blockIdx.x * 128;

    extern __shared__ __align__(128) char smem[];
    uint32_t sbase = smem_u32(smem);

    int tid  = threadIdx.x;
    int wid  = tid >> 5, lane = tid & 31;
    int wm0  = (wid & 3) * 32;         // 4 m-warps
    int wn0  = (wid >> 2) * 32;        // 4 n-warps

    const bf16* gAh = Ahi + e * aES + (size_t)m0 * K;
    const bf16* gAl = Alo + e * aES + (size_t)m0 * K;
    const bf16* gBh = Bhi + e * bES + (size_t)n0 * K;
    const bf16* gBl = Blo + e * bES + (size_t)n0 * K;

    int nT = K >> 5;                   // BK = 32

    // accumulators: 2 m-tiles x 4 n-tiles x 4 regs
    float acc[2][4][4];
    #pragma unroll
    for (int i = 0; i < 2; i++)
        #pragma unroll
        for (int j = 0; j < 4; j++)
            #pragma unroll
            for (int q = 0; q < 4; q++) acc[i][j][q] = 0.f;

    // loader: each of 512 threads covers exactly chunk tid of each 512-chunk tile
    int lr = tid >> 2, lc = tid & 3;

    #define ISSUE(t)                                                     \
        do {                                                             \
            if ((t) < nT) {                                              \
                uint32_t sb_ = sbase + ((t) % NSTAGE) * STAGEB;          \
                uint32_t so_ = swz(lr, lc);                              \
                size_t go_ = (size_t)lr * K + (size_t)(t) * 32 + lc * 8; \
                CPASYNC16(sb_ + 0 * TILEB + so_, gAh + go_);             \
                CPASYNC16(sb_ + 1 * TILEB + so_, gAl + go_);             \
                CPASYNC16(sb_ + 2 * TILEB + so_, gBh + go_);             \
                CPASYNC16(sb_ + 3 * TILEB + so_, gBl + go_);             \
            }                                                            \
            CP_COMMIT();                                                 \
        } while (0)

    ISSUE(0);
    ISSUE(1);

    for (int t = 0; t < nT; t++) {
        CP_WAIT(1);            // stage t complete (only t+1 may be pending)
        __syncthreads();       // also orders prior compute before next ISSUE

        uint32_t sb  = sbase + (t % NSTAGE) * STAGEB;
        uint32_t sAh = sb, sAl = sb + TILEB, sBh = sb + 2 * TILEB, sBl = sb + 3 * TILEB;

        #pragma unroll
        for (int ks = 0; ks < 2; ks++) {
            int kc = ks * 2;
            uint32_t Ah[2][4], Al[2][4], Bh[2][4], Bl[2][4];
            #pragma unroll
            for (int mi = 0; mi < 2; mi++) {
                int row = wm0 + mi * 16 + (lane & 15);
                int c   = kc + (lane >> 4);
                uint32_t off = swz(row, c);
                LDMX4(Ah[mi], sAh + off);
                LDMX4(Al[mi], sAl + off);
            }
            #pragma unroll
            for (int bi = 0; bi < 2; bi++) {
                int row = wn0 + bi * 16 + ((lane >> 4) & 1) * 8 + (lane & 7);
                int c   = kc + ((lane >> 3) & 1);
                uint32_t off = swz(row, c);
                LDMX4(Bh[bi], sBh + off);
                LDMX4(Bl[bi], sBl + off);
            }
            #pragma unroll
            for (int mi = 0; mi < 2; mi++) {
                #pragma unroll
                for (int ni = 0; ni < 4; ni++) {
                    uint32_t* bh = &Bh[ni >> 1][(ni & 1) * 2];
                    uint32_t* bl = &Bl[ni >> 1][(ni & 1) * 2];
                    MMA16816(acc[mi][ni], Ah[mi], bh);   // hi*hi
                    MMA16816(acc[mi][ni], Ah[mi], bl);   // hi*lo
                    MMA16816(acc[mi][ni], Al[mi], bh);   // lo*hi
                }
            }
        }
        ISSUE(t + 2);
    }

    // epilogue
    const float* biasE = bias + e * biasES;
    #pragma unroll
    for (int mi = 0; mi < 2; mi++) {
        #pragma unroll
        for (int ni = 0; ni < 4; ni++) {
            int gr0 = m0 + wm0 + mi * 16 + (lane >> 2);
            int gr1 = gr0 + 8;
            int gc  = n0 + wn0 + ni * 8 + (lane & 3) * 2;
            float bv0 = __ldg(biasE + gc), bv1 = __ldg(biasE + gc + 1);
            float f00 = fmaxf(acc[mi][ni][0] + bv0, 0.f);
            float f01 = fmaxf(acc[mi][ni][1] + bv1, 0.f);
            float f10 = fmaxf(acc[mi][ni][2] + bv0, 0.f);
            float f11 = fmaxf(acc[mi][ni][3] + bv1, 0.f);
            if (mode == 0) {
                __nv_bfloat162 h0 = __floats2bfloat162_rn(f00, f01);
                __nv_bfloat162 h1 = __floats2bfloat162_rn(f10, f11);
                __nv_bfloat162 l0 = __floats2bfloat162_rn(
                    f00 - __bfloat162float(h0.x), f01 - __bfloat162float(h0.y));
                __nv_bfloat162 l1 = __floats2bfloat162_rn(
                    f10 - __bfloat162float(h1.x), f11 - __bfloat162float(h1.y));
                size_t o0 = e * oES + (size_t)gr0 * HIDC + gc;
                size_t o1 = e * oES + (size_t)gr1 * HIDC + gc;
                *(__nv_bfloat162*)(OutHi + o0) = h0;
                *(__nv_bfloat162*)(OutHi + o1) = h1;
                *(__nv_bfloat162*)(OutLo + o0) = l0;
                *(__nv_bfloat162*)(OutLo + o1) = l1;
            } else {
                size_t o0 = e * oES + (size_t)gr0 * HIDC + gc;
                size_t o1 = e * oES + (size_t)gr1 * HIDC + gc;
                *(float2*)(OutF + o0) = make_float2(f00, f01);
                *(float2*)(OutF + o1) = make_float2(f10, f11);
            }
        }
    }
    #undef ISSUE
}

// ---------------- Gram-Schmidt + gather (reads compacted O via pos) ---------
template <int M>
__device__ __forceinline__ void blockReduce(float* vals, float (*red)[8], int tid)
{
    int lane = tid & 31, w = tid >> 5;
    #pragma unroll
    for (int i = 0; i < M; i++) {
        float v = vals[i];
        #pragma unroll
        for (int o = 16; o; o >>= 1) v += __shfl_xor_sync(0xffffffffu, v, o);
        if (lane == 0) red[i][w] = v;
    }
    __syncthreads();
    #pragma unroll
    for (int i = 0; i < M; i++) {
        float s = 0.f;
        #pragma unroll
        for (int ww = 0; ww < 8; ww++) s += red[i][ww];
        vals[i] = s;
    }
    __syncthreads();
}

__global__ void gs_kernel(const float* __restrict__ O,
                          const float* __restrict__ gate,
                          const int*   __restrict__ idx,
                          const int*   __restrict__ pos,
                          float* __restrict__ out)
{
    __shared__ float red[3][8];
    int n   = blockIdx.x;
    int tid = threadIdx.x;
    int kmax = idx[n];
    float g  = gate[n];
    const size_t NH = (size_t)N_TOK * HIDC;
    const float* base = O + (size_t)pos[n] * HIDC + tid * 8;

    float b[4][8];
    float t[8], w[8];

    #pragma unroll
    for (int i = 0; i < 4; i++) {
        if (i > kmax) break;
        float4 p0 = *(const float4*)(base + (size_t)i * NH);
        float4 p1 = *(const float4*)(base + (size_t)i * NH + 4);
        t[0]=p0.x; t[1]=p0.y; t[2]=p0.z; t[3]=p0.w;
        t[4]=p1.x; t[5]=p1.y; t[6]=p1.z; t[7]=p1.w;

        float c[3] = {0.f, 0.f, 0.f};
        if (i > 0) {
            #pragma unroll
            for (int j = 0; j < 3; j++) {
                if (j < i) {
                    float d = 0.f;
                    #pragma unroll
                    for (int q = 0; q < 8; q++) d += t[q] * b[j][q];
                    c[j] = d;
                }
            }
            blockReduce<3>(c, red, tid);
        }
        float ss[1] = {0.f};
        #pragma unroll
        for (int q = 0; q < 8; q++) {
            float wv = t[q];
            #pragma unroll
            for (int j = 0; j < 3; j++) if (j < i) wv -= c[j] * b[j][q];
            w[q] = wv;
            ss[0] += wv * wv;
        }
        blockReduce<1>(ss, red, tid);
        float inv = rsqrtf(ss[0]);
        #pragma unroll
        for (int q = 0; q < 8; q++) b[i][q] = w[q] * inv;

        if (i == kmax) {
            float4 o0, o1;
            o0.x = g * b[i][0]; o0.y = g * b[i][1];
            o0.z = g * b[i][2]; o0.w = g * b[i][3];
            o1.x = g * b[i][4]; o1.y = g * b[i][5];
            o1.z = g * b[i][6]; o1.w = g * b[i][7];
            float* op = out + (size_t)n * HIDC + tid * 8;
            *(float4*)(op)     = o0;
            *(float4*)(op + 4) = o1;
        }
    }
}

// ---------------------------------------------------------------------------
extern "C" void kernel_launch(void* const* d_in, const int* in_sizes, int n_in,
                              void* d_out, int out_size)
{
    const float* X    = (const float*)d_in[0];
    const int*   task = (const int*)  d_in[1];
    const float* temb = (const float*)d_in[2];
    const float* rmat = (const float*)d_in[3];
    const float* W1   = (const float*)d_in[4];
    const float* b1   = (const float*)d_in[5];
    const float* W2   = (const float*)d_in[6];
    const float* b2   = (const float*)d_in[7];
    float* out = (float*)d_out;

    bf16 *Xhi, *Xlo, *W1Thi, *W1Tlo, *W2Thi, *W2Tlo, *Hhi, *Hlo;
    float *O, *gate;
    int *idx, *pos, *perm, *cntge;
    cudaGetSymbolAddress((void**)&Xhi,   g_Xhi);
    cudaGetSymbolAddress((void**)&Xlo,   g_Xlo);
    cudaGetSymbolAddress((void**)&W1Thi, g_W1Thi);
    cudaGetSymbolAddress((void**)&W1Tlo, g_W1Tlo);
    cudaGetSymbolAddress((void**)&W2Thi, g_W2Thi);
    cudaGetSymbolAddress((void**)&W2Tlo, g_W2Tlo);
    cudaGetSymbolAddress((void**)&Hhi,   g_Hhi);
    cudaGetSymbolAddress((void**)&Hlo,   g_Hlo);
    cudaGetSymbolAddress((void**)&O,     g_O);
    cudaGetSymbolAddress((void**)&gate,  g_gate);
    cudaGetSymbolAddress((void**)&idx,   g_idx);
    cudaGetSymbolAddress((void**)&pos,   g_pos);
    cudaGetSymbolAddress((void**)&perm,  g_perm);
    cudaGetSymbolAddress((void**)&cntge, g_cntge);

    cudaFuncSetAttribute(gemm_hmma, cudaFuncAttributeMaxDynamicSharedMemorySize,
                         GEMM_SMEM);

    // 1) router -> gate/idx/reg_loss
    router_kernel<<<N_TOK / 8, 256>>>(X, task, temb, rmat, gate, idx,
                                      out + (size_t)N_TOK * HIDC);

    // 2) compaction (single block counting sort, descending idx)
    compact_kernel<<<1, 1024>>>(idx, pos, perm, cntge);

    // 3) fused preps: gather/split X + transpose/split W1, W2
    prep_kernel<<<32768, 256>>>(X, perm, Xhi, Xlo,
                                W1, W1Thi, W1Tlo,
                                W2, W2Thi, W2Tlo);

    dim3 gg(HIDC / 128, N_TOK / 128, NE);
    // 4) GEMM1: H = relu(Xs @ W1 + b1) -> bf16 hi/lo   [profiled slot]
    gemm_hmma<<<gg, 512, GEMM_SMEM>>>(
        Xhi, Xlo, W1Thi, W1Tlo, b1, Hhi, Hlo, nullptr, cntge,
        IN_DIMC, 0,
        (size_t)0, (size_t)HIDC * IN_DIMC, (size_t)HIDC, (size_t)N_TOK * HIDC);
    // 5) GEMM2: O = relu(H @ W2 + b2) -> f32
    gemm_hmma<<<gg, 512, GEMM_SMEM>>>(
        Hhi, Hlo, W2Thi, W2Tlo, b2, nullptr, nullptr, O, cntge,
        HIDC, 1,
        (size_t)N_TOK * HIDC, (size_t)HIDC * HIDC, (size_t)HIDC, (size_t)N_TOK * HIDC);

    // 6) Gram-Schmidt + gather
    gs_kernel<<<N_TOK, 256>>>(O, gate, idx, pos, out);
}